// round 11
// baseline (speedup 1.0000x reference)
#include <cuda_runtime.h>

#define BATCH    131072
#define INP      5
#define HID      64
#define NEXP     40
#define OUTD     5
#define ROWS     64               // batch rows per block
#define NTHREADS 256
#define NBLK     (BATCH / ROWS)   // 2048

// zdup: ROWS rows of 132 floats (128 used: 64 k-values duplicated as (z,z) pairs)
#define ZSTRIDE_F 132             // floats per zdup row (16B-aligned, bank-staggered)
#define ZDUP_BYTES (ROWS * ZSTRIDE_F * 4)        // 33792
#define WSM_BYTES  (HID * HID * 4)               // 16384
#define POOL_BYTES (2880 * 4)                    // 11520 (polw 2560 + xs 320 | decw 320)
#define BSM_BYTES  (HID * 4)                     // 256
#define ACTS_BYTES (ROWS * 4)                    // 256
#define SMEM_TOTAL (ZDUP_BYTES + WSM_BYTES + POOL_BYTES + BSM_BYTES + ACTS_BYTES)  // 62208

typedef unsigned int u32;
typedef unsigned long long u64;

// ---------------------------------------------------------------------------
// Packed dual-fp32 FMA (SASS FFMA2) — lane-wise fma.rn, bit-exact vs scalar.
// ---------------------------------------------------------------------------
__device__ __forceinline__ void ffma2(u64& d, u64 a, u64 b) {
    asm("fma.rn.f32x2 %0, %1, %2, %0;" : "+l"(d) : "l"(a), "l"(b));
}
__device__ __forceinline__ float lo32f(u64 v) { return __uint_as_float((u32)v); }
__device__ __forceinline__ float hi32f(u64 v) { return __uint_as_float((u32)(v >> 32)); }

// ---------------------------------------------------------------------------
// JAX threefry2x32 with key = jax.random.key(1) -> (k1,k2) = (0,1)
// ---------------------------------------------------------------------------
__device__ __forceinline__ u32 rotl32(u32 x, int d) { return (x << d) | (x >> (32 - d)); }

__device__ __forceinline__ void threefry2x32_key01(u32 c0, u32 c1, u32& o0, u32& o1) {
    const u32 ks0 = 0u, ks1 = 1u, ks2 = 0x1BD11BDBu;  // 0x1BD11BDA ^ 0 ^ 1
    u32 x0 = c0 + ks0, x1 = c1 + ks1;
#define TFR(r) { x0 += x1; x1 = rotl32(x1, (r)); x1 ^= x0; }
    TFR(13) TFR(15) TFR(26) TFR(6)   x0 += ks1; x1 += ks2 + 1u;
    TFR(17) TFR(29) TFR(16) TFR(24)  x0 += ks2; x1 += ks0 + 2u;
    TFR(13) TFR(15) TFR(26) TFR(6)   x0 += ks0; x1 += ks1 + 3u;
    TFR(17) TFR(29) TFR(16) TFR(24)  x0 += ks1; x1 += ks2 + 4u;
    TFR(13) TFR(15) TFR(26) TFR(6)   x0 += ks2; x1 += ks0 + 5u;
#undef TFR
    o0 = x0; o1 = x1;
}

__device__ __forceinline__ float jax_gumbel32(u32 idx) {
    u32 a, b;
    threefry2x32_key01(0u, idx, a, b);
    u32 bits = a ^ b;
    float f = __uint_as_float(0x3f800000u | (bits >> 9)) - 1.0f;   // [0, 1)
    float u = fmaxf(f, 1.17549435e-38f);                            // minval = tiny
    return -logf(-logf(u));
}

// ---------------------------------------------------------------------------
// Fused kernel: encoder -> policy(softmax+categorical) -> 40-expert layer
// Phase C uses packed f32x2 FMAs; out[b] from register accumulators.
// ---------------------------------------------------------------------------
__global__ __launch_bounds__(NTHREADS)
void trizrl_kernel(const float* __restrict__ x,
                   const float* __restrict__ enc_w, const float* __restrict__ enc_b,
                   const float* __restrict__ triz_w, const float* __restrict__ triz_b,
                   const float* __restrict__ pol_w, const float* __restrict__ pol_b,
                   const float* __restrict__ dec_w, const float* __restrict__ dec_b,
                   float* __restrict__ out) {
    extern __shared__ __align__(16) char smem_raw[];
    float* zf   = (float*)smem_raw;                         // zdup, float view
    u64*   zdU  = (u64*)smem_raw;                           // zdup, (z,z) pair view
    float* wsm  = (float*)(smem_raw + ZDUP_BYTES);
    float* pool = (float*)(smem_raw + ZDUP_BYTES + WSM_BYTES);
    float* bsm  = (float*)(smem_raw + ZDUP_BYTES + WSM_BYTES + POOL_BYTES);
    int*   acts = (int*)  (smem_raw + ZDUP_BYTES + WSM_BYTES + POOL_BYTES + BSM_BYTES);

    float* polw = pool;          // [0:2560)    pol_w staged, Phase A/B
    float* xs   = pool + 2560;   // [2560:2880) x rows staged, Phase A
    float* decw = pool;          // [0:320)     dec_w staged, Phase C (polw dead)

    // Output layout: concat(out[B,5], probs[B,40], actions[B], h[B,40,64]) fp32
    float* out_out   = out;
    float* out_probs = out + (size_t)BATCH * OUTD;
    float* out_act   = out_probs + (size_t)BATCH * NEXP;
    float* out_h     = out_act + (size_t)BATCH;

    const int tid  = threadIdx.x;
    const int blk  = blockIdx.x;
    const int brow = blk * ROWS;

    // ---- stage x rows (strided, FULL range); init out rows to dec_b ----
    for (int i = tid; i < ROWS * INP; i += NTHREADS) {
        xs[i] = x[(size_t)brow * INP + i];
        out_out[(size_t)brow * OUTD + i] = __ldg(&dec_b[i % OUTD]);
    }
    for (int i = tid; i < HID * NEXP; i += NTHREADS) polw[i] = pol_w[i];
    __syncthreads();

    // ---- Phase A: z = tanh(x @ enc_w + enc_b) -> zdup as (z,z) 64-bit pairs ----
    {
        const int j  = tid & (HID - 1);
        const int r0 = tid >> 6;          // 0..3
        float ew0 = __ldg(&enc_w[0 * HID + j]);
        float ew1 = __ldg(&enc_w[1 * HID + j]);
        float ew2 = __ldg(&enc_w[2 * HID + j]);
        float ew3 = __ldg(&enc_w[3 * HID + j]);
        float ew4 = __ldg(&enc_w[4 * HID + j]);
        float eb  = __ldg(&enc_b[j]);
#pragma unroll
        for (int it = 0; it < ROWS / 4; ++it) {
            int r = it * 4 + r0;
            const float* xr = &xs[r * INP];
            float a = eb;
            a = fmaf(xr[0], ew0, a);
            a = fmaf(xr[1], ew1, a);
            a = fmaf(xr[2], ew2, a);
            a = fmaf(xr[3], ew3, a);
            a = fmaf(xr[4], ew4, a);
            float zv = tanhf(a);
            u32 zb = __float_as_uint(zv);
            zdU[r * (ZSTRIDE_F / 2) + j] = ((u64)zb << 32) | zb;   // (z,z)
        }
    }
    __syncthreads();

    // ---- Phase B: logits, gumbel-max categorical, softmax probs ----
    {
        const int r = tid >> 2;         // row within block, 4 lanes per row
        const int q = tid & 3;          // expert chunk: e in [q*10, q*10+10)
        const int b = brow + r;
        const float* zr = &zf[r * ZSTRIDE_F];   // z at even float offsets

        float lg[10];
#pragma unroll
        for (int j = 0; j < 10; ++j) {
            int e = q * 10 + j;
            float acc = __ldg(&pol_b[e]);
#pragma unroll
            for (int k = 0; k < HID; ++k) acc = fmaf(zr[2 * k], polw[k * NEXP + e], acc);
            lg[j] = acc;
        }

        const float NEG_INF = __int_as_float(0xff800000);
        float best = NEG_INF; int bestE = 0x7fffffff; float m = NEG_INF;
#pragma unroll
        for (int j = 0; j < 10; ++j) {
            int e = q * 10 + j;
            float g = jax_gumbel32((u32)(b * NEXP + e));
            float y = lg[j] + g;
            if (y > best) { best = y; bestE = e; }   // strict > keeps first index
            m = fmaxf(m, lg[j]);
        }
#pragma unroll
        for (int off = 1; off < 4; off <<= 1) {
            float ob = __shfl_xor_sync(0xffffffffu, best,  off, 4);
            int   oe = __shfl_xor_sync(0xffffffffu, bestE, off, 4);
            float om = __shfl_xor_sync(0xffffffffu, m,     off, 4);
            if (ob > best || (ob == best && oe < bestE)) { best = ob; bestE = oe; }
            m = fmaxf(m, om);
        }
        float s = 0.0f;
#pragma unroll
        for (int j = 0; j < 10; ++j) s += expf(lg[j] - m);
#pragma unroll
        for (int off = 1; off < 4; off <<= 1) s += __shfl_xor_sync(0xffffffffu, s, off, 4);
#pragma unroll
        for (int j = 0; j < 10; ++j) {
            int e = q * 10 + j;
            out_probs[(size_t)b * NEXP + e] = expf(lg[j] - m) / s;
        }
        if (q == 0) { out_act[b] = (float)bestE; acts[r] = bestE; }
    }
    __syncthreads();

    // ---- stage dec_w into smem (strided; overlays dead polw) ----
    for (int i = tid; i < HID * OUTD; i += NTHREADS) decw[i] = dec_w[i];  // decw[f*5+j]

    // ---- Phase C: h + fused register-direct decode, packed f32x2 FMAs ----
    const int ct = tid & 15;        // column tile: f0 = ct*4
    const int rt = tid >> 4;        // row tile:    r0 = rt*4
    const int f0 = ct * 4;
    const int r0 = rt * 4;

    const ulonglong2* zv2 = (const ulonglong2*)smem_raw;     // 33 ull2 per row
    const ulonglong2* wv2 = (const ulonglong2*)wsm;          // 16 ull2 per k-row

    for (int e = 0; e < NEXP; ++e) {
        __syncthreads();   // previous expert's wsm readers done / decw staged
        {
            const float4* wg = (const float4*)(triz_w + (size_t)e * HID * HID);
            float4* w4s = (float4*)wsm;
#pragma unroll
            for (int i = 0; i < 4; ++i) w4s[tid + i * NTHREADS] = wg[tid + i * NTHREADS];
            if (tid < HID) bsm[tid] = __ldg(&triz_b[e * HID + tid]);
        }
        __syncthreads();

        // acc2[r][p]: packed pair of accumulators for cols (f0+2p, f0+2p+1)
        u64 acc2[4][2];
#pragma unroll
        for (int i = 0; i < 4; ++i) { acc2[i][0] = 0ull; acc2[i][1] = 0ull; }

#pragma unroll 4
        for (int kk = 0; kk < HID / 2; ++kk) {      // 2 k-values per iteration
            ulonglong2 w0 = wv2[(2 * kk + 0) * 16 + ct];   // ((w[f0],w[f0+1]),(w[f0+2],w[f0+3])) @ k
            ulonglong2 w1 = wv2[(2 * kk + 1) * 16 + ct];   // same @ k+1
            ulonglong2 za = zv2[(r0 + 0) * 33 + kk];       // ((z_k,z_k),(z_{k+1},z_{k+1}))
            ulonglong2 zb = zv2[(r0 + 1) * 33 + kk];
            ulonglong2 zc = zv2[(r0 + 2) * 33 + kk];
            ulonglong2 zd = zv2[(r0 + 3) * 33 + kk];

            ffma2(acc2[0][0], za.x, w0.x); ffma2(acc2[0][1], za.x, w0.y);
            ffma2(acc2[1][0], zb.x, w0.x); ffma2(acc2[1][1], zb.x, w0.y);
            ffma2(acc2[2][0], zc.x, w0.x); ffma2(acc2[2][1], zc.x, w0.y);
            ffma2(acc2[3][0], zd.x, w0.x); ffma2(acc2[3][1], zd.x, w0.y);

            ffma2(acc2[0][0], za.y, w1.x); ffma2(acc2[0][1], za.y, w1.y);
            ffma2(acc2[1][0], zb.y, w1.x); ffma2(acc2[1][1], zb.y, w1.y);
            ffma2(acc2[2][0], zc.y, w1.x); ffma2(acc2[2][1], zc.y, w1.y);
            ffma2(acc2[3][0], zd.y, w1.x); ffma2(acc2[3][1], zd.y, w1.y);
        }

        float b0 = bsm[f0 + 0], b1 = bsm[f0 + 1], b2 = bsm[f0 + 2], b3 = bsm[f0 + 3];
#pragma unroll
        for (int ri = 0; ri < 4; ++ri) {
            float4 o;
            o.x = fmaxf(lo32f(acc2[ri][0]) + b0, 0.0f);
            o.y = fmaxf(hi32f(acc2[ri][0]) + b1, 0.0f);
            o.z = fmaxf(lo32f(acc2[ri][1]) + b2, 0.0f);
            o.w = fmaxf(hi32f(acc2[ri][1]) + b3, 0.0f);
            int row = r0 + ri;
            size_t gb = (size_t)(brow + row);
            *(float4*)&out_h[((gb * NEXP + e) * HID) + f0] = o;

            // Register-direct decode of the selected expert (no h readback).
            if (acts[row] == e) {
#pragma unroll
                for (int j = 0; j < OUTD; ++j) {
                    float v;
                    v = o.x * decw[(f0 + 0) * OUTD + j];
                    v = fmaf(o.y, decw[(f0 + 1) * OUTD + j], v);
                    v = fmaf(o.z, decw[(f0 + 2) * OUTD + j], v);
                    v = fmaf(o.w, decw[(f0 + 3) * OUTD + j], v);
                    atomicAdd(&out_out[gb * OUTD + j], v);
                }
            }
        }
    }
}

// ---------------------------------------------------------------------------
extern "C" void kernel_launch(void* const* d_in, const int* in_sizes, int n_in,
                              void* d_out, int out_size) {
    const float* x      = (const float*)d_in[0];
    const float* enc_w  = (const float*)d_in[1];
    const float* enc_b  = (const float*)d_in[2];
    const float* triz_w = (const float*)d_in[3];
    const float* triz_b = (const float*)d_in[4];
    const float* pol_w  = (const float*)d_in[5];
    const float* pol_b  = (const float*)d_in[6];
    const float* dec_w  = (const float*)d_in[7];
    const float* dec_b  = (const float*)d_in[8];
    float* out = (float*)d_out;

    cudaFuncSetAttribute(trizrl_kernel,
                         cudaFuncAttributeMaxDynamicSharedMemorySize, SMEM_TOTAL);
    trizrl_kernel<<<NBLK, NTHREADS, SMEM_TOTAL>>>(x, enc_w, enc_b, triz_w, triz_b,
                                                  pol_w, pol_b, dec_w, dec_b, out);
}

// round 12
// speedup vs baseline: 1.4032x; 1.4032x over previous
#include <cuda_runtime.h>
#include <cuda_bf16.h>

#define BATCH    131072
#define INP      5
#define HID      64
#define NEXP     40
#define OUTD     5
#define ROWS     64               // batch rows per block
#define NTHREADS 256
#define NBLK     (BATCH / ROWS)   // 2048

// ---- dynamic smem layout (bytes) ----
#define ZF_STRIDE 66                       // fp32 z row stride (floats)
#define KB_STRIDE 160                      // bf16 row stride BYTES (80 halves): stride/4 % 32 == 8
#define ZF_OFF   0
#define ZF_SZ    (ROWS * ZF_STRIDE * 4)    // 16896
#define ZH_OFF   (ZF_OFF + ZF_SZ)          // 16896
#define ZH_SZ    (ROWS * KB_STRIDE)        // 10240
#define ZL_OFF   (ZH_OFF + ZH_SZ)          // 27136
#define ZL_SZ    ZH_SZ
#define WH_OFF   (ZL_OFF + ZL_SZ)          // 37376
#define WH_SZ    (HID * KB_STRIDE)         // 10240
#define WL_OFF   (WH_OFF + WH_SZ)          // 47616
#define WL_SZ    WH_SZ
#define POOL_OFF (WL_OFF + WL_SZ)          // 57856
#define POOL_SZ  (2880 * 4)                // polw 2560f + xs 320f
#define BSM_OFF  (POOL_OFF + POOL_SZ)      // 69376
#define ACTS_OFF (BSM_OFF + 256)           // 69632
#define SMEM_TOTAL (ACTS_OFF + 256)        // 69888

typedef unsigned int u32;

// k-permutation: within each k16 block store halves in order (2t,2t+1,2t+8,2t+9)
// so fragment pairs (a0,a2)/(b0,b1) are 8B-contiguous -> one LDS.64.
__device__ __forceinline__ int kperm(int k) {
    return (k & 48) | ((k & 6) << 1) | ((k & 8) >> 2) | (k & 1);
}

// m16n8k16 row.col bf16 MMA, fp32 accumulate (accumulates in place).
__device__ __forceinline__ void mma_bf16(float* c, u32 a0, u32 a1, u32 a2, u32 a3,
                                         u32 b0, u32 b1) {
    asm volatile(
        "mma.sync.aligned.m16n8k16.row.col.f32.bf16.bf16.f32 "
        "{%0,%1,%2,%3}, {%4,%5,%6,%7}, {%8,%9}, {%0,%1,%2,%3};"
        : "+f"(c[0]), "+f"(c[1]), "+f"(c[2]), "+f"(c[3])
        : "r"(a0), "r"(a1), "r"(a2), "r"(a3), "r"(b0), "r"(b1));
}

// ---------------------------------------------------------------------------
// JAX threefry2x32, key = jax.random.key(1) -> (0,1); partitionable counters.
// ---------------------------------------------------------------------------
__device__ __forceinline__ u32 rotl32(u32 x, int d) { return (x << d) | (x >> (32 - d)); }

__device__ __forceinline__ void threefry2x32_key01(u32 c0, u32 c1, u32& o0, u32& o1) {
    const u32 ks0 = 0u, ks1 = 1u, ks2 = 0x1BD11BDBu;
    u32 x0 = c0 + ks0, x1 = c1 + ks1;
#define TFR(r) { x0 += x1; x1 = rotl32(x1, (r)); x1 ^= x0; }
    TFR(13) TFR(15) TFR(26) TFR(6)   x0 += ks1; x1 += ks2 + 1u;
    TFR(17) TFR(29) TFR(16) TFR(24)  x0 += ks2; x1 += ks0 + 2u;
    TFR(13) TFR(15) TFR(26) TFR(6)   x0 += ks0; x1 += ks1 + 3u;
    TFR(17) TFR(29) TFR(16) TFR(24)  x0 += ks1; x1 += ks2 + 4u;
    TFR(13) TFR(15) TFR(26) TFR(6)   x0 += ks2; x1 += ks0 + 5u;
#undef TFR
    o0 = x0; o1 = x1;
}

__device__ __forceinline__ float jax_gumbel32(u32 idx) {
    u32 a, b;
    threefry2x32_key01(0u, idx, a, b);
    u32 bits = a ^ b;
    float f = __uint_as_float(0x3f800000u | (bits >> 9)) - 1.0f;
    float u = fmaxf(f, 1.17549435e-38f);
    return -logf(-logf(u));
}

// ---------------------------------------------------------------------------
__global__ __launch_bounds__(NTHREADS)
void trizrl_kernel(const float* __restrict__ x,
                   const float* __restrict__ enc_w, const float* __restrict__ enc_b,
                   const float* __restrict__ triz_w, const float* __restrict__ triz_b,
                   const float* __restrict__ pol_w, const float* __restrict__ pol_b,
                   const float* __restrict__ dec_w, const float* __restrict__ dec_b,
                   float* __restrict__ out) {
    extern __shared__ __align__(16) char smem[];
    float*          zf   = (float*)(smem + ZF_OFF);
    __nv_bfloat16*  zh   = (__nv_bfloat16*)(smem + ZH_OFF);
    __nv_bfloat16*  zl   = (__nv_bfloat16*)(smem + ZL_OFF);
    __nv_bfloat16*  wh   = (__nv_bfloat16*)(smem + WH_OFF);
    __nv_bfloat16*  wl   = (__nv_bfloat16*)(smem + WL_OFF);
    float*          pool = (float*)(smem + POOL_OFF);
    float*          bsm  = (float*)(smem + BSM_OFF);
    int*            acts = (int*)(smem + ACTS_OFF);

    float* polw = pool;          // [0:2560)
    float* xs   = pool + 2560;   // [2560:2880)

    // Output: concat(out[B,5], probs[B,40], actions[B], h[B,40,64]) fp32
    float* out_out   = out;
    float* out_probs = out + (size_t)BATCH * OUTD;
    float* out_act   = out_probs + (size_t)BATCH * NEXP;
    float* out_h     = out_act + (size_t)BATCH;

    const int tid  = threadIdx.x;
    const int blk  = blockIdx.x;
    const int brow = blk * ROWS;

    for (int i = tid; i < ROWS * INP; i += NTHREADS)
        xs[i] = x[(size_t)brow * INP + i];
    for (int i = tid; i < HID * NEXP; i += NTHREADS) polw[i] = pol_w[i];
    __syncthreads();

    // ---- Phase A: z = tanh(x@enc_w+enc_b) -> zf (fp32) + zh/zl (bf16 split, k-permuted)
    {
        const int j  = tid & (HID - 1);
        const int r0 = tid >> 6;          // 0..3
        const int pj = kperm(j);
        float ew0 = __ldg(&enc_w[0 * HID + j]);
        float ew1 = __ldg(&enc_w[1 * HID + j]);
        float ew2 = __ldg(&enc_w[2 * HID + j]);
        float ew3 = __ldg(&enc_w[3 * HID + j]);
        float ew4 = __ldg(&enc_w[4 * HID + j]);
        float eb  = __ldg(&enc_b[j]);
#pragma unroll
        for (int it = 0; it < ROWS / 4; ++it) {
            int r = it * 4 + r0;
            const float* xr = &xs[r * INP];
            float a = eb;
            a = fmaf(xr[0], ew0, a);
            a = fmaf(xr[1], ew1, a);
            a = fmaf(xr[2], ew2, a);
            a = fmaf(xr[3], ew3, a);
            a = fmaf(xr[4], ew4, a);
            float zv = tanhf(a);
            zf[r * ZF_STRIDE + j] = zv;
            __nv_bfloat16 hi = __float2bfloat16(zv);
            __nv_bfloat16 lo = __float2bfloat16(zv - __bfloat162float(hi));
            zh[r * 80 + pj] = hi;
            zl[r * 80 + pj] = lo;
        }
    }
    __syncthreads();

    // ---- Phase B: logits (exact fp32), gumbel-max categorical, softmax probs ----
    {
        const int r = tid >> 2;
        const int q = tid & 3;
        const int b = brow + r;
        const float* zr = &zf[r * ZF_STRIDE];

        float lg[10];
#pragma unroll
        for (int j = 0; j < 10; ++j) {
            int e = q * 10 + j;
            float acc = __ldg(&pol_b[e]);
#pragma unroll
            for (int k = 0; k < HID; ++k) acc = fmaf(zr[k], polw[k * NEXP + e], acc);
            lg[j] = acc;
        }

        const float NEG_INF = __int_as_float(0xff800000);
        float best = NEG_INF; int bestE = 0x7fffffff; float m = NEG_INF;
#pragma unroll
        for (int j = 0; j < 10; ++j) {
            int e = q * 10 + j;
            float g = jax_gumbel32((u32)(b * NEXP + e));
            float y = lg[j] + g;
            if (y > best) { best = y; bestE = e; }
            m = fmaxf(m, lg[j]);
        }
#pragma unroll
        for (int off = 1; off < 4; off <<= 1) {
            float ob = __shfl_xor_sync(0xffffffffu, best,  off, 4);
            int   oe = __shfl_xor_sync(0xffffffffu, bestE, off, 4);
            float om = __shfl_xor_sync(0xffffffffu, m,     off, 4);
            if (ob > best || (ob == best && oe < bestE)) { best = ob; bestE = oe; }
            m = fmaxf(m, om);
        }
        float s = 0.0f;
#pragma unroll
        for (int j = 0; j < 10; ++j) s += expf(lg[j] - m);
#pragma unroll
        for (int off = 1; off < 4; off <<= 1) s += __shfl_xor_sync(0xffffffffu, s, off, 4);
#pragma unroll
        for (int j = 0; j < 10; ++j) {
            int e = q * 10 + j;
            out_probs[(size_t)b * NEXP + e] = expf(lg[j] - m) / s;
        }
        if (q == 0) { out_act[b] = (float)bestE; acts[r] = bestE; }
    }

    // ---- Phase C: h = relu(Z @ W[e] + b[e]) via bf16-split m16n8k16 MMA ----
    const int wid = tid >> 5;          // 0..7
    const int mt  = wid & 3;           // m-tile: rows mt*16..+16
    const int nh  = wid >> 2;          // n-half: cols nh*32..+32
    const int ln  = tid & 31;
    const int g   = ln >> 2;           // fragment group row / B col
    const int tg  = ln & 3;

    const char* zhB = smem + ZH_OFF;
    const char* zlB = smem + ZL_OFF;
    const char* whB = smem + WH_OFF;
    const char* wlB = smem + WL_OFF;
    const int rowA0 = mt * 16 + g;
    const int rowA1 = rowA0 + 8;

    for (int e = 0; e < NEXP; ++e) {
        __syncthreads();   // previous expert's tiles fully consumed
        // Stage W[e] transposed [f][k], bf16 hi/lo, k-permuted rows.
        {
            const float4* wg = (const float4*)(triz_w + (size_t)e * HID * HID);
#pragma unroll
            for (int i = 0; i < 4; ++i) {
                int idx = tid + i * NTHREADS;       // 0..1023
                int k  = idx & 63;
                int fq = idx >> 6;                  // 0..15
                float4 v = wg[k * 16 + fq];
                int pk = kperm(k);
                float vv[4] = {v.x, v.y, v.z, v.w};
#pragma unroll
                for (int j = 0; j < 4; ++j) {
                    int f = fq * 4 + j;
                    __nv_bfloat16 hi = __float2bfloat16(vv[j]);
                    __nv_bfloat16 lo = __float2bfloat16(vv[j] - __bfloat162float(hi));
                    wh[f * 80 + pk] = hi;
                    wl[f * 80 + pk] = lo;
                }
            }
            if (tid < HID) bsm[tid] = __ldg(&triz_b[e * HID + tid]);
        }
        __syncthreads();

        float c[4][4];
#pragma unroll
        for (int nt = 0; nt < 4; ++nt)
#pragma unroll
            for (int i = 0; i < 4; ++i) c[nt][i] = 0.0f;

#pragma unroll
        for (int s = 0; s < 4; ++s) {               // k16 steps
            const int ko = s * 32 + tg * 8;         // byte offset within row
            uint2 ah_lo = *(const uint2*)(zhB + rowA0 * KB_STRIDE + ko);  // {a0,a2}
            uint2 ah_hi = *(const uint2*)(zhB + rowA1 * KB_STRIDE + ko);  // {a1,a3}
            uint2 al_lo = *(const uint2*)(zlB + rowA0 * KB_STRIDE + ko);
            uint2 al_hi = *(const uint2*)(zlB + rowA1 * KB_STRIDE + ko);
#pragma unroll
            for (int nt = 0; nt < 4; ++nt) {
                int n = nh * 32 + nt * 8 + g;
                uint2 bh = *(const uint2*)(whB + n * KB_STRIDE + ko);     // {b0,b1}
                uint2 bl = *(const uint2*)(wlB + n * KB_STRIDE + ko);
                mma_bf16(c[nt], ah_lo.x, ah_hi.x, ah_lo.y, ah_hi.y, bh.x, bh.y);
                mma_bf16(c[nt], ah_lo.x, ah_hi.x, ah_lo.y, ah_hi.y, bl.x, bl.y);
                mma_bf16(c[nt], al_lo.x, al_hi.x, al_lo.y, al_hi.y, bh.x, bh.y);
            }
        }

        // Epilogue: bias + relu + store h
        size_t gb0 = (size_t)(brow + rowA0);
        size_t gb1 = (size_t)(brow + rowA1);
#pragma unroll
        for (int nt = 0; nt < 4; ++nt) {
            int c0i = nh * 32 + nt * 8 + 2 * tg;
            float bb0 = bsm[c0i], bb1 = bsm[c0i + 1];
            float2 o0, o1;
            o0.x = fmaxf(c[nt][0] + bb0, 0.0f);
            o0.y = fmaxf(c[nt][1] + bb1, 0.0f);
            o1.x = fmaxf(c[nt][2] + bb0, 0.0f);
            o1.y = fmaxf(c[nt][3] + bb1, 0.0f);
            *(float2*)&out_h[(gb0 * NEXP + e) * HID + c0i] = o0;
            *(float2*)&out_h[(gb1 * NEXP + e) * HID + c0i] = o1;
        }
    }
    __syncthreads();   // h of this block's rows globally visible block-wide

    // ---- Phase D: out = h[b, action] @ dec_w + dec_b (readback of own rows) ----
    if (tid < ROWS) {
        const int r = tid;
        const int b = brow + r;
        const int a = acts[r];
        const float* hrow = &out_h[((size_t)b * NEXP + a) * HID];
        float a0 = __ldg(&dec_b[0]), a1 = __ldg(&dec_b[1]), a2 = __ldg(&dec_b[2]),
              a3 = __ldg(&dec_b[3]), a4 = __ldg(&dec_b[4]);
        for (int k = 0; k < HID; ++k) {
            float hv = hrow[k];
            a0 = fmaf(hv, __ldg(&dec_w[k * OUTD + 0]), a0);
            a1 = fmaf(hv, __ldg(&dec_w[k * OUTD + 1]), a1);
            a2 = fmaf(hv, __ldg(&dec_w[k * OUTD + 2]), a2);
            a3 = fmaf(hv, __ldg(&dec_w[k * OUTD + 3]), a3);
            a4 = fmaf(hv, __ldg(&dec_w[k * OUTD + 4]), a4);
        }
        size_t ob = (size_t)b * OUTD;
        out_out[ob + 0] = a0; out_out[ob + 1] = a1; out_out[ob + 2] = a2;
        out_out[ob + 3] = a3; out_out[ob + 4] = a4;
    }
}

// ---------------------------------------------------------------------------
extern "C" void kernel_launch(void* const* d_in, const int* in_sizes, int n_in,
                              void* d_out, int out_size) {
    const float* x      = (const float*)d_in[0];
    const float* enc_w  = (const float*)d_in[1];
    const float* enc_b  = (const float*)d_in[2];
    const float* triz_w = (const float*)d_in[3];
    const float* triz_b = (const float*)d_in[4];
    const float* pol_w  = (const float*)d_in[5];
    const float* pol_b  = (const float*)d_in[6];
    const float* dec_w  = (const float*)d_in[7];
    const float* dec_b  = (const float*)d_in[8];
    float* out = (float*)d_out;

    cudaFuncSetAttribute(trizrl_kernel,
                         cudaFuncAttributeMaxDynamicSharedMemorySize, SMEM_TOTAL);
    trizrl_kernel<<<NBLK, NTHREADS, SMEM_TOTAL>>>(x, enc_w, enc_b, triz_w, triz_b,
                                                  pol_w, pol_b, dec_w, dec_b, out);
}